// round 13
// baseline (speedup 1.0000x reference)
#include <cuda_runtime.h>

// Census loss, pair-symmetric, f32x2-packed, 2 adjacent pixels/thread.
// t = 1 - 0.1*rc, rc = 1/(0.1+e^2), e = cx-cy, c = d*rsqrt(7.29+d^2),
// d = g3(b)-g3(a), g3 = r+g+b (/3 folded into 0.81*9=7.29).
// Interior thread (48 pairs, weight 2): res = 96 - 0.2*sum(rc).
// Single launch: threadfence reduction, self-wrapping counter, no memset.
// R12 fix: halo loader writes the FULL 20-float2 pitch (floats 38-39 were
// uninitialized in R11 and read by tx=15 threads).

#define IMG   256
#define IMG2  65536
#define SW2   20   // smem pitch in float2 (40 floats: 4 left halo + 32 + 4)
#define SWR   22   // 16 tile rows + 6 halo
#define NF2   440  // 22 rows * 20 float2 per row (full pitch)
#define NBLK  1024

typedef unsigned long long ull;

__device__ float        g_part[NBLK];
__device__ unsigned int g_cnt = 0;

__device__ __forceinline__ float frsqrt_a(float x){ float r; asm("rsqrt.approx.f32 %0, %1;" : "=f"(r) : "f"(x)); return r; }
__device__ __forceinline__ float frcp_a  (float x){ float r; asm("rcp.approx.f32 %0, %1;"   : "=f"(r) : "f"(x)); return r; }

__device__ __forceinline__ ull pk(float lo, float hi){ ull r; asm("mov.b64 %0, {%1, %2};" : "=l"(r) : "f"(lo), "f"(hi)); return r; }
__device__ __forceinline__ ull p2(float2 v){ return pk(v.x, v.y); }
__device__ __forceinline__ float2 upk(ull v){ float2 f; asm("mov.b64 {%0, %1}, %2;" : "=f"(f.x), "=f"(f.y) : "l"(v)); return f; }
__device__ __forceinline__ ull fma2(ull a, ull b, ull c){ ull r; asm("fma.rn.f32x2 %0, %1, %2, %3;" : "=l"(r) : "l"(a), "l"(b), "l"(c)); return r; }
__device__ __forceinline__ ull mul2(ull a, ull b){ ull r; asm("mul.rn.f32x2 %0, %1, %2;" : "=l"(r) : "l"(a), "l"(b)); return r; }
__device__ __forceinline__ ull sub2(ull a, ull b){ ull r; asm("sub.rn.f32x2 %0, %1, %2;" : "=l"(r) : "l"(a), "l"(b)); return r; }

// packed rc = 1/(0.1+e^2) for two pixel-pairs (fused rational, 3 MUFU/pair)
__device__ __forceinline__ float2 pair_rc2(ull nbx, ull nby, ull cenx, ull ceny,
                                           ull C729, ull C01)
{
    ull dX = sub2(nbx, cenx);
    ull dY = sub2(nby, ceny);
    ull aX = fma2(dX, dX, C729);
    ull aY = fma2(dY, dY, C729);
    float2 a = upk(aX);
    ull rX = pk(frsqrt_a(a.x), frsqrt_a(a.y));
    float2 b = upk(aY);
    ull rY = pk(frsqrt_a(b.x), frsqrt_a(b.y));
    ull cx = mul2(dX, rX);
    ull cy = mul2(dY, rY);
    ull e  = sub2(cx, cy);
    ull dn = fma2(e, e, C01);
    float2 d = upk(dn);
    float2 rc;
    rc.x = frcp_a(d.x);
    rc.y = frcp_a(d.y);
    return rc;
}

template<bool BORDER>
__device__ __forceinline__ float census_body(const float2* __restrict__ bx,
                                             const float2* __restrict__ by,
                                             int r, int c0)
{
    const ull C729 = pk(7.29f, 7.29f);
    const ull C01  = pk(0.1f, 0.1f);

    float vrow[4], vcw[8];
    float va0 = 0.f, va1 = 0.f;
    if (BORDER) {
#pragma unroll
        for (int d = 0; d < 4; d++) vrow[d] = ((unsigned)(r + d - 3) < 250u) ? 1.f : 0.f;   // v(row r+d)
#pragma unroll
        for (int j = 0; j < 8; j++) vcw[j] = ((unsigned)(c0 - 6 + j) < 250u) ? 1.f : 0.f;   // v(col c0+j-3)
        va0 = vrow[0] * vcw[3];
        va1 = vrow[0] * vcw[4];
    }

    float accA = 0.f, accB = 0.f, accw = 0.f;

    // ---- center row (dy = 0): center pair is aligned f2 at bx[2] ----
    ull cenx, ceny;
    {
        float2 x2 = bx[2], x3 = bx[3], x4 = bx[4];
        float2 y2 = by[2], y3 = by[3], y4 = by[4];
        cenx = p2(x2); ceny = p2(y2);

        {   // dx=1
            float2 rc = pair_rc2(pk(x2.y, x3.x), pk(y2.y, y3.x), cenx, ceny, C729, C01);
            if (BORDER) { float w0 = fmaf(vrow[0], vcw[4], va0), w1 = fmaf(vrow[0], vcw[5], va1);
                          accw += w0 + w1; accA = fmaf(w0, rc.x, accA); accB = fmaf(w1, rc.y, accB); }
            else { accA += rc.x; accB += rc.y; }
        }
        {   // dx=2 (aligned)
            float2 rc = pair_rc2(p2(x3), p2(y3), cenx, ceny, C729, C01);
            if (BORDER) { float w0 = fmaf(vrow[0], vcw[5], va0), w1 = fmaf(vrow[0], vcw[6], va1);
                          accw += w0 + w1; accA = fmaf(w0, rc.x, accA); accB = fmaf(w1, rc.y, accB); }
            else { accA += rc.x; accB += rc.y; }
        }
        {   // dx=3
            float2 rc = pair_rc2(pk(x3.y, x4.x), pk(y3.y, y4.x), cenx, ceny, C729, C01);
            if (BORDER) { float w0 = fmaf(vrow[0], vcw[6], va0), w1 = fmaf(vrow[0], vcw[7], va1);
                          accw += w0 + w1; accA = fmaf(w0, rc.x, accA); accB = fmaf(w1, rc.y, accB); }
            else { accA += rc.x; accB += rc.y; }
        }
    }

    // ---- dy = 1..3: dx = -3..3 ----
#pragma unroll
    for (int dy = 1; dy < 4; dy++) {
        const float2* rx = bx + dy * SW2;
        const float2* ry = by + dy * SW2;
        float2 x0 = rx[0], x1 = rx[1], x2 = rx[2], x3 = rx[3], x4 = rx[4];
        float2 y0 = ry[0], y1 = ry[1], y2 = ry[2], y3 = ry[3], y4 = ry[4];

#pragma unroll
        for (int j = 0; j < 7; j++) {
            ull nbx, nby;
            switch (j) {
                case 0: nbx = pk(x0.y, x1.x); nby = pk(y0.y, y1.x); break;  // dx=-3
                case 1: nbx = p2(x1);         nby = p2(y1);         break;  // dx=-2
                case 2: nbx = pk(x1.y, x2.x); nby = pk(y1.y, y2.x); break;  // dx=-1
                case 3: nbx = p2(x2);         nby = p2(y2);         break;  // dx= 0
                case 4: nbx = pk(x2.y, x3.x); nby = pk(y2.y, y3.x); break;  // dx=+1
                case 5: nbx = p2(x3);         nby = p2(y3);         break;  // dx=+2
                default:nbx = pk(x3.y, x4.x); nby = pk(y3.y, y4.x); break;  // dx=+3
            }
            float2 rc = pair_rc2(nbx, nby, cenx, ceny, C729, C01);
            if (BORDER) {
                float w0 = fmaf(vrow[dy], vcw[j], va0);
                float w1 = fmaf(vrow[dy], vcw[j + 1], va1);
                accw += w0 + w1;
                accA = fmaf(w0, rc.x, accA);
                accB = fmaf(w1, rc.y, accB);
            } else {
                accA += rc.x;
                accB += rc.y;
            }
        }
    }

    float s = accA + accB;
    return BORDER ? fmaf(-0.1f, s, accw) : fmaf(-0.2f, s, 96.f);
}

__global__ __launch_bounds__(256, 4)
void census_loss_kernel(const float* __restrict__ x,
                        const float* __restrict__ y,
                        float* __restrict__ out)
{
    __shared__ __align__(16) float sgx[SWR * SW2 * 2];
    __shared__ __align__(16) float sgy[SWR * SW2 * 2];

    const int b    = blockIdx.z;
    const int row0 = blockIdx.y * 16;
    const int col0 = blockIdx.x * 32;
    const int tid  = threadIdx.y * 16 + threadIdx.x;

    const float2* xb2 = (const float2*)(x + (size_t)b * 3 * IMG2);
    const float2* yb2 = (const float2*)(y + (size_t)b * 3 * IMG2);

    // 3*grayscale tile + halo, float2-vectorized, FULL 20-float2 pitch per row
    const int colbase2 = (col0 - 4) >> 1;   // float2 col index of window start
#pragma unroll
    for (int it = 0; it < 2; it++) {
        int i = tid + it * 256;
        if (i < NF2) {
            int lr  = i / SW2;
            int lc2 = i - lr * SW2;
            int gr  = row0 - 3 + lr;
            int gc2 = colbase2 + lc2;
            float2 gx = make_float2(0.f, 0.f), gy = gx;
            if ((unsigned)gr < 256u && (unsigned)gc2 < 128u) {
                int o = gr * 128 + gc2;
                float2 a0 = xb2[o], a1 = xb2[o + 32768], a2 = xb2[o + 65536];
                float2 b0 = yb2[o], b1 = yb2[o + 32768], b2 = yb2[o + 65536];
                gx = make_float2(a0.x + a1.x + a2.x, a0.y + a1.y + a2.y);
                gy = make_float2(b0.x + b1.x + b2.x, b0.y + b1.y + b2.y);
            }
            ((float2*)sgx)[i] = gx;
            ((float2*)sgy)[i] = gy;
        }
    }
    __syncthreads();

    const int tx = threadIdx.x;          // 0..15 -> pixel cols 2tx, 2tx+1
    const int ty = threadIdx.y;          // 0..15 -> pixel row
    const int r  = row0 + ty;
    const int c0 = col0 + 2 * tx;

    const float2* bx = (const float2*)sgx + (ty + 3) * SW2 + tx;
    const float2* by = (const float2*)sgy + (ty + 3) * SW2 + tx;

    // per-thread interior test: all 48 pairs fully valid
    const bool tin = ((unsigned)(r - 3) < 247u) & ((unsigned)(c0 - 6) < 243u);

    float acc = tin ? census_body<false>(bx, by, r, c0)
                    : census_body<true >(bx, by, r, c0);

    // warp + block reduction
#pragma unroll
    for (int s = 16; s > 0; s >>= 1)
        acc += __shfl_xor_sync(0xFFFFFFFFu, acc, s);

    __shared__ float wsum[8];
    __shared__ bool  last;
    if ((tid & 31) == 0) wsum[tid >> 5] = acc;
    __syncthreads();
    if (tid < 8) {
        float v = wsum[tid];
        v += __shfl_xor_sync(0xFFu, v, 4);
        v += __shfl_xor_sync(0xFFu, v, 2);
        v += __shfl_xor_sync(0xFFu, v, 1);
        if (tid == 0) {
            const int bid = (blockIdx.z * 16 + blockIdx.y) * 8 + blockIdx.x;
            g_part[bid] = v;
            __threadfence();
            last = (atomicInc(&g_cnt, NBLK - 1) == NBLK - 1);   // wraps to 0 each launch
        }
    }
    __syncthreads();

    if (last) {
        // deterministic fixed-order final reduction of 1024 partials
        float s = __ldcg(&g_part[tid])       + __ldcg(&g_part[tid + 256])
                + __ldcg(&g_part[tid + 512]) + __ldcg(&g_part[tid + 768]);
#pragma unroll
        for (int sh = 16; sh > 0; sh >>= 1)
            s += __shfl_xor_sync(0xFFFFFFFFu, s, sh);
        if ((tid & 31) == 0) wsum[tid >> 5] = s;
        __syncthreads();
        if (tid < 8) {
            float v = wsum[tid];
            v += __shfl_xor_sync(0xFFu, v, 4);
            v += __shfl_xor_sync(0xFFu, v, 2);
            v += __shfl_xor_sync(0xFFu, v, 1);
            if (tid == 0)
                *out = v * (1.f / 25690112.f);   // 1/(49*8*256*256)
        }
    }
}

extern "C" void kernel_launch(void* const* d_in, const int* in_sizes, int n_in,
                              void* d_out, int out_size)
{
    const float* x = (const float*)d_in[0];
    const float* y = (const float*)d_in[1];
    float* out = (float*)d_out;

    dim3 block(16, 16, 1);
    dim3 grid(8, 16, 8);   // 1024 blocks
    census_loss_kernel<<<grid, block>>>(x, y, out);
}

// round 14
// speedup vs baseline: 1.2486x; 1.2486x over previous
#include <cuda_runtime.h>

// Census loss, pair-symmetric, f32x2-packed, 2 adjacent pixels/thread.
// t = 1 - 0.1*rc, rc = 1/(0.1+e^2), e = cx-cy, c = d*rsqrt(7.29+d^2),
// d = g3(b)-g3(a), g3 = r+g+b (/3 folded into 0.81*9=7.29).
// Interior thread (48 pairs, weight 2): res = 96 - 0.2*sum(rc).
// Dual shifted float4 smem layouts: A[k] = {gx,gx,gy,gy} for pixel pair
// (2k-4,2k-3)+col0, B[k] = same shifted +1 px. Every dx neighbor pair is one
// aligned ld.shared.v2.b64 -> zero packing MOVs in the inner loop.

#define IMG   256
#define IMG2  65536
#define PITCH 20        // float4 per row
#define SROWS 22        // 16 tile rows + 6 halo
#define NEL   440       // SROWS * PITCH

typedef unsigned long long ull;

__device__ __forceinline__ float frsqrt_a(float x){ float r; asm("rsqrt.approx.f32 %0, %1;" : "=f"(r) : "f"(x)); return r; }
__device__ __forceinline__ float frcp_a  (float x){ float r; asm("rcp.approx.f32 %0, %1;"   : "=f"(r) : "f"(x)); return r; }

__device__ __forceinline__ ull pk(float lo, float hi){ ull r; asm("mov.b64 %0, {%1, %2};" : "=l"(r) : "f"(lo), "f"(hi)); return r; }
__device__ __forceinline__ float2 upk(ull v){ float2 f; asm("mov.b64 {%0, %1}, %2;" : "=f"(f.x), "=f"(f.y) : "l"(v)); return f; }
__device__ __forceinline__ ull fma2(ull a, ull b, ull c){ ull r; asm("fma.rn.f32x2 %0, %1, %2, %3;" : "=l"(r) : "l"(a), "l"(b), "l"(c)); return r; }
__device__ __forceinline__ ull mul2(ull a, ull b){ ull r; asm("mul.rn.f32x2 %0, %1, %2;" : "=l"(r) : "l"(a), "l"(b)); return r; }
__device__ __forceinline__ ull sub2(ull a, ull b){ ull r; asm("sub.rn.f32x2 %0, %1, %2;" : "=l"(r) : "l"(a), "l"(b)); return r; }

// one 128-bit shared load -> x-image pair (a) and y-image pair (b)
__device__ __forceinline__ void lds128(const float4* p, ull& a, ull& b){
    asm("ld.shared.v2.b64 {%0, %1}, [%2];"
        : "=l"(a), "=l"(b) : "l"(__cvta_generic_to_shared(p)));
}

// packed rc = 1/(0.1+e^2) for two pixel-pairs (fused rational, 3 MUFU/pair)
__device__ __forceinline__ float2 pair_rc2(ull nbx, ull nby, ull cenx, ull ceny,
                                           ull C729, ull C01)
{
    ull dX = sub2(nbx, cenx);
    ull dY = sub2(nby, ceny);
    ull aX = fma2(dX, dX, C729);
    ull aY = fma2(dY, dY, C729);
    float2 a = upk(aX);
    ull rX = pk(frsqrt_a(a.x), frsqrt_a(a.y));
    float2 b = upk(aY);
    ull rY = pk(frsqrt_a(b.x), frsqrt_a(b.y));
    ull cx = mul2(dX, rX);
    ull cy = mul2(dY, rY);
    ull e  = sub2(cx, cy);
    ull dn = fma2(e, e, C01);
    float2 d = upk(dn);
    float2 rc;
    rc.x = frcp_a(d.x);
    rc.y = frcp_a(d.y);
    return rc;
}

template<bool BORDER>
__device__ __forceinline__ float census_body(const float4* __restrict__ Ab,
                                             const float4* __restrict__ Bb,
                                             int r, int c0)
{
    const ull C729 = pk(7.29f, 7.29f);
    const ull C01  = pk(0.1f, 0.1f);

    float vrow[4], vcw[8];
    float va0 = 0.f, va1 = 0.f;
    if (BORDER) {
#pragma unroll
        for (int d = 0; d < 4; d++) vrow[d] = ((unsigned)(r + d - 3) < 250u) ? 1.f : 0.f;   // valid(row r+d)
#pragma unroll
        for (int j = 0; j < 8; j++) vcw[j] = ((unsigned)(c0 - 6 + j) < 250u) ? 1.f : 0.f;   // valid(col c0+j-3)
        va0 = vrow[0] * vcw[3];
        va1 = vrow[0] * vcw[4];
    }

    float accA = 0.f, accB = 0.f, accw = 0.f;

    ull cenx, ceny;
    lds128(Ab + 2, cenx, ceny);

    // ---- dy = 0: dx = 1 (B[2]), dx = 2 (A[3]), dx = 3 (B[3]) ----
    {
        ull nbx, nby;
        lds128(Bb + 2, nbx, nby);
        float2 rc = pair_rc2(nbx, nby, cenx, ceny, C729, C01);
        if (BORDER) { float w0 = fmaf(vrow[0], vcw[4], va0), w1 = fmaf(vrow[0], vcw[5], va1);
                      accw += w0 + w1; accA = fmaf(w0, rc.x, accA); accB = fmaf(w1, rc.y, accB); }
        else { accA += rc.x; accB += rc.y; }

        lds128(Ab + 3, nbx, nby);
        rc = pair_rc2(nbx, nby, cenx, ceny, C729, C01);
        if (BORDER) { float w0 = fmaf(vrow[0], vcw[5], va0), w1 = fmaf(vrow[0], vcw[6], va1);
                      accw += w0 + w1; accA = fmaf(w0, rc.x, accA); accB = fmaf(w1, rc.y, accB); }
        else { accA += rc.x; accB += rc.y; }

        lds128(Bb + 3, nbx, nby);
        rc = pair_rc2(nbx, nby, cenx, ceny, C729, C01);
        if (BORDER) { float w0 = fmaf(vrow[0], vcw[6], va0), w1 = fmaf(vrow[0], vcw[7], va1);
                      accw += w0 + w1; accA = fmaf(w0, rc.x, accA); accB = fmaf(w1, rc.y, accB); }
        else { accA += rc.x; accB += rc.y; }
    }

    // ---- dy = 1..3: j = 0..6 <-> dx = j-3 ----
    // j even -> B[tx + j/2], j odd -> A[tx + (j+1)/2]
#pragma unroll
    for (int dy = 1; dy < 4; dy++) {
        const float4* Ar = Ab + dy * PITCH;
        const float4* Br = Bb + dy * PITCH;
#pragma unroll
        for (int j = 0; j < 7; j++) {
            ull nbx, nby;
            if (j & 1) lds128(Ar + ((j + 1) >> 1), nbx, nby);
            else       lds128(Br + (j >> 1),       nbx, nby);
            float2 rc = pair_rc2(nbx, nby, cenx, ceny, C729, C01);
            if (BORDER) {
                float w0 = fmaf(vrow[dy], vcw[j], va0);
                float w1 = fmaf(vrow[dy], vcw[j + 1], va1);
                accw += w0 + w1;
                accA = fmaf(w0, rc.x, accA);
                accB = fmaf(w1, rc.y, accB);
            } else {
                accA += rc.x;
                accB += rc.y;
            }
        }
    }

    float s = accA + accB;
    return BORDER ? fmaf(-0.1f, s, accw) : fmaf(-0.2f, s, 96.f);
}

__global__ __launch_bounds__(256, 4)
void census_loss_kernel(const float* __restrict__ x,
                        const float* __restrict__ y,
                        float* __restrict__ out)
{
    __shared__ __align__(16) float4 sA[NEL];
    __shared__ __align__(16) float4 sB[NEL];

    const int b    = blockIdx.z;
    const int row0 = blockIdx.y * 16;
    const int col0 = blockIdx.x * 32;
    const int tid  = threadIdx.y * 16 + threadIdx.x;

    const float2* xb2 = (const float2*)(x + (size_t)b * 3 * IMG2);
    const float2* yb2 = (const float2*)(y + (size_t)b * 3 * IMG2);

    // Pass 1: layout A. A[r][k] = pixels (col0-4+2k, col0-4+2k+1), rows row0-3+r
    const int colbase2 = (col0 - 4) >> 1;   // gmem float2 col index of A[.][0]
#pragma unroll
    for (int it = 0; it < 2; it++) {
        int i = tid + it * 256;
        if (i < NEL) {
            int lr = i / PITCH;
            int k  = i - lr * PITCH;
            int gr = row0 - 3 + lr;
            int gc2 = colbase2 + k;
            float2 gx = make_float2(0.f, 0.f), gy = gx;
            if ((unsigned)gr < 256u && (unsigned)gc2 < 128u) {
                int o = gr * 128 + gc2;
                float2 a0 = xb2[o], a1 = xb2[o + 32768], a2 = xb2[o + 65536];
                float2 b0 = yb2[o], b1 = yb2[o + 32768], b2 = yb2[o + 65536];
                gx = make_float2(a0.x + a1.x + a2.x, a0.y + a1.y + a2.y);
                gy = make_float2(b0.x + b1.x + b2.x, b0.y + b1.y + b2.y);
            }
            sA[i] = make_float4(gx.x, gx.y, gy.x, gy.y);
        }
    }
    __syncthreads();

    // Pass 2: layout B (shifted +1 pixel). B[i] = {A[i].y, A[i+1].x, A[i].w, A[i+1].z}
#pragma unroll
    for (int it = 0; it < 2; it++) {
        int i = tid + it * 256;
        if (i < NEL) {
            int k = i % PITCH;
            float4 a0 = sA[i];
            float4 a1 = (k < PITCH - 1) ? sA[i + 1] : make_float4(0.f, 0.f, 0.f, 0.f);
            sB[i] = make_float4(a0.y, a1.x, a0.w, a1.z);
        }
    }
    __syncthreads();

    const int tx = threadIdx.x;          // 0..15 -> pixel cols 2tx, 2tx+1
    const int ty = threadIdx.y;          // 0..15 -> pixel row
    const int r  = row0 + ty;
    const int c0 = col0 + 2 * tx;

    // thread's center pair lives at A[tx+2] (pixels col0+2tx, col0+2tx+1)
    const float4* Ab = sA + (ty + 3) * PITCH + tx;
    const float4* Bb = sB + (ty + 3) * PITCH + tx;

    const bool interior = (blockIdx.x - 1u < 6u) & (blockIdx.y - 1u < 14u);

    float acc = interior ? census_body<false>(Ab, Bb, r, c0)
                         : census_body<true >(Ab, Bb, r, c0);

    // warp + block reduction
#pragma unroll
    for (int s = 16; s > 0; s >>= 1)
        acc += __shfl_xor_sync(0xFFFFFFFFu, acc, s);

    __shared__ float wsum[8];
    if ((tid & 31) == 0) wsum[tid >> 5] = acc;
    __syncthreads();
    if (tid < 8) {
        float v = wsum[tid];
        v += __shfl_xor_sync(0xFFu, v, 4);
        v += __shfl_xor_sync(0xFFu, v, 2);
        v += __shfl_xor_sync(0xFFu, v, 1);
        if (tid == 0)
            atomicAdd(out, v * (1.f / 25690112.f));   // 1/(49*8*256*256)
    }
}

extern "C" void kernel_launch(void* const* d_in, const int* in_sizes, int n_in,
                              void* d_out, int out_size)
{
    const float* x = (const float*)d_in[0];
    const float* y = (const float*)d_in[1];
    float* out = (float*)d_out;

    cudaMemsetAsync(out, 0, sizeof(float));

    dim3 block(16, 16, 1);
    dim3 grid(8, 16, 8);   // 1024 blocks
    census_loss_kernel<<<grid, block>>>(x, y, out);
}